// round 14
// baseline (speedup 1.0000x reference)
#include <cuda_runtime.h>
#include <cstdint>

#define TLEN 4096
#define NH 32
#define HS 64
#define DIM (NH*HS)
#define DEPTH 8
#define STRIDE 336   // floats/slot: w64|k64|a64|b64|r64|v4|pad

// grid=256 (32 heads x 8 octants of 8 rows), block=64 = 2 warps.
// ~2 blocks co-resident per SM -> 2 warps per SMSP (wid%4 = 0,1 for both
// blocks) => cross-warp latency hiding, which no previous config had.
// Warp w: 4 rows (one per 8-lane group g); lane owns row (oct*8+w*4+g)'s
// 8-float j-slice (lane8*8), f32x2-packed. Per-warp cp.async ring DEPTH=8,
// 8x-unrolled loop, compile-time slots, deferred y-reduction.

__device__ __forceinline__ uint32_t smem_u32(const void* p) {
    return (uint32_t)__cvta_generic_to_shared(p);
}

typedef unsigned long long u64;

#define MUL2(d,a,b)   asm("mul.rn.f32x2 %0, %1, %2;"     : "=l"(d) : "l"(a), "l"(b))
#define FMA2(d,a,b,c) asm("fma.rn.f32x2 %0, %1, %2, %3;" : "=l"(d) : "l"(a), "l"(b), "l"(c))
#define PACK2(d,lo,hi)   asm("mov.b64 %0, {%1, %2};" : "=l"(d) : "f"(lo), "f"(hi))
#define UNPACK2(lo,hi,v) asm("mov.b64 {%0, %1}, %2;" : "=f"(lo), "=f"(hi) : "l"(v))

#define DOT8(res, X, Y) do { \
    u64 _p; MUL2(_p, X[0], Y[0]); FMA2(_p, X[1], Y[1], _p); \
    FMA2(_p, X[2], Y[2], _p);     FMA2(_p, X[3], Y[3], _p); \
    float _lo, _hi; UNPACK2(_lo, _hi, _p); res = _lo + _hi; } while(0)

#define RED8(x) do { \
    x += __shfl_xor_sync(0xffffffffu, x, 1); \
    x += __shfl_xor_sync(0xffffffffu, x, 2); \
    x += __shfl_xor_sync(0xffffffffu, x, 4); } while(0)

#define LD4x2(dst, ptr) do { \
    const ulonglong2* _p = (const ulonglong2*)(ptr); \
    ulonglong2 _x0 = _p[0], _x1 = _p[1]; \
    dst[0]=_x0.x; dst[1]=_x0.y; dst[2]=_x1.x; dst[3]=_x1.y; } while(0)

__global__ void __launch_bounds__(64, 2) wkv7_kernel(
    const float* __restrict__ rr, const float* __restrict__ ww,
    const float* __restrict__ kk, const float* __restrict__ vv_,
    const float* __restrict__ aa, const float* __restrict__ bb,
    const float* __restrict__ s0, float* __restrict__ y, float* __restrict__ sout)
{
    const int blk   = blockIdx.x;
    const int h     = blk >> 3;           // head
    const int oct   = blk & 7;            // octant (8 rows)
    const int tid   = threadIdx.x;
    const int warp  = tid >> 5;
    const int lane  = tid & 31;
    const int lane8 = lane & 7;
    const int g     = lane >> 3;
    const int j0    = lane8 * 8;
    const int hbase = h * HS;
    const int row   = oct * 8 + warp * 4 + g;   // my single row (0..63)

    __shared__ __align__(16) float ring[2][DEPTH][STRIDE];

    // State: one row's 8-float j-slice
    u64 S[4];
    LD4x2(S, s0 + ((size_t)h * HS + row) * HS + j0);

    // cp.async lane routing (3 x 16B per lane per step)
    const float *g1, *g2, *g3 = 0;
    uint32_t o1, o2, o3 = 0;
    if (lane < 16) { g1 = ww + hbase + lane * 4;        o1 = 0   + lane * 4; }
    else           { g1 = kk + hbase + (lane - 16) * 4; o1 = 64  + (lane - 16) * 4; }
    if (lane < 16) { g2 = aa + hbase + lane * 4;        o2 = 128 + lane * 4; }
    else           { g2 = bb + hbase + (lane - 16) * 4; o2 = 192 + (lane - 16) * 4; }
    if (lane < 16)       { g3 = rr  + hbase + lane * 4;               o3 = 256 + lane * 4; }
    else if (lane == 16) { g3 = vv_ + hbase + oct * 8 + warp * 4;     o3 = 320; }

#define ISSUE(tt, ss) do { \
    size_t _off = (size_t)(tt) * DIM; \
    uint32_t _sb = smem_u32(&ring[warp][ss][0]); \
    asm volatile("cp.async.cg.shared.global [%0], [%1], 16;" :: "r"(_sb + o1*4u), "l"(g1 + _off)); \
    asm volatile("cp.async.cg.shared.global [%0], [%1], 16;" :: "r"(_sb + o2*4u), "l"(g2 + _off)); \
    if (g3) asm volatile("cp.async.cg.shared.global [%0], [%1], 16;" :: "r"(_sb + o3*4u), "l"(g3 + _off)); \
    asm volatile("cp.async.commit_group;"); \
} while(0)

    #pragma unroll
    for (int i = 0; i < DEPTH; i++) ISSUE(i, i);

    // a_0 direct from gmem
    u64 a2[4];
    LD4x2(a2, aa + hbase + j0);

    float yv = 0.f;                              // deferred y partial
    float* const ystore = y + hbase + row;

// Step body: SLOT = slot of t, SLOTN = slot of t+1 (a-prefetch).
#define STEPBODY(T, SLOT, SLOTN) do { \
    const float* sl  = &ring[warp][SLOT][0]; \
    const float* sln = &ring[warp][SLOTN][0]; \
    /* sa dot + butterfly (all 4 groups reduce concurrently) */ \
    float sa; \
    DOT8(sa, S, a2); \
    RED8(sa); \
    /* deferred y_{T-1} (independent; fills shfl slack) */ \
    { \
        float u = yv; \
        RED8(u); \
        int tprev = (T) - ((T) != 0); \
        if (lane8 == 0) ystore[(size_t)tprev * DIM] = u; \
    } \
    u64 w2[4], k2[4], b2[4], r2[4]; \
    LD4x2(w2, sl + j0); \
    LD4x2(k2, sl + 64 + j0); \
    LD4x2(b2, sl + 192 + j0); \
    LD4x2(r2, sl + 256 + j0); \
    const float v = sl[320 + g]; \
    LD4x2(a2, sln + 128 + j0); \
    u64 vb, sab; \
    PACK2(vb, v, v); \
    PACK2(sab, sa, sa); \
    _Pragma("unroll") \
    for (int i = 0; i < 4; i++) { \
        u64 t0; MUL2(t0, S[i], w2[i]); \
        FMA2(t0, vb, k2[i], t0); \
        FMA2(S[i], sab, b2[i], t0); \
    } \
    u64 yp; \
    MUL2(yp, S[0], r2[0]); FMA2(yp, S[1], r2[1], yp); \
    FMA2(yp, S[2], r2[2], yp); FMA2(yp, S[3], r2[3], yp); \
    { float l, hh; UNPACK2(l, hh, yp); yv = l + hh; } \
} while(0)

    for (int tb = 0; tb < TLEN - DEPTH; tb += DEPTH) {
        #pragma unroll
        for (int u = 0; u < DEPTH; u++) {
            const int t = tb + u;
            asm volatile("cp.async.wait_group 6;");
            __syncwarp();
            STEPBODY(t, u, (u + 1) & (DEPTH - 1));
            ISSUE(t + DEPTH, u);
        }
    }

    asm volatile("cp.async.wait_group 0;");
    __syncwarp();
    #pragma unroll
    for (int u = 0; u < DEPTH; u++) {
        const int t = TLEN - DEPTH + u;
        STEPBODY(t, u, (u + 1) & (DEPTH - 1));   // final a2 prefetch unused
    }

    // Epilogue: y_{TLEN-1}
    {
        RED8(yv);
        if (lane8 == 0) ystore[(size_t)(TLEN - 1) * DIM] = yv;
    }

    // Final state
    {
        float* sp = sout + ((size_t)h * HS + row) * HS + j0;
        ulonglong2* p = (ulonglong2*)sp;
        ulonglong2 x;
        x.x = S[0]; x.y = S[1]; p[0] = x;
        x.x = S[2]; x.y = S[3]; p[1] = x;
    }
}

extern "C" void kernel_launch(void* const* d_in, const int* in_sizes, int n_in,
                              void* d_out, int out_size) {
    int o = (n_in >= 8) ? 1 : 0;
    const float* r  = (const float*)d_in[o + 0];
    const float* w  = (const float*)d_in[o + 1];
    const float* k  = (const float*)d_in[o + 2];
    const float* v  = (const float*)d_in[o + 3];
    const float* a  = (const float*)d_in[o + 4];
    const float* b  = (const float*)d_in[o + 5];
    const float* s0 = (const float*)d_in[o + 6];

    float* y    = (float*)d_out;                  // x: [T, H, 1, N]
    float* sout = y + (size_t)TLEN * DIM;         // state2_out: [H, N, N]

    wkv7_kernel<<<256, 64>>>(r, w, k, v, a, b, s0, y, sout);
}

// round 15
// speedup vs baseline: 1.0526x; 1.0526x over previous
#include <cuda_runtime.h>
#include <cstdint>

#define TLEN 4096
#define NH 32
#define HS 64
#define DIM (NH*HS)
#define DEPTH 8
#define STRIDE 336   // floats/slot: w64|k64|a64|b64|r64|v16

// grid=128 (32 heads x 4 quarters of 16 rows), block = ONE warp.
// j-split 4: lane4 = lane&3 owns a 16-float j-slice; group g = lane>>2
// (8 groups) owns rows (q*16 + g*2, +1). Each lane: 2 rows x 16 floats of
// state (8 u64 f32x2 per row). Reductions are over 4 lanes: RED4 = 2 shfls.
// Per-step MIO: 21 LDS + 8 SHFL + 3 cp.async + 1 STG (~33 ops). The fma pipe
// (80 FMA2 x rt2 = 160cyc) is the intended bound. Ring DEPTH=8, 8x unroll.

__device__ __forceinline__ uint32_t smem_u32(const void* p) {
    return (uint32_t)__cvta_generic_to_shared(p);
}

typedef unsigned long long u64;

#define MUL2(d,a,b)   asm("mul.rn.f32x2 %0, %1, %2;"     : "=l"(d) : "l"(a), "l"(b))
#define FMA2(d,a,b,c) asm("fma.rn.f32x2 %0, %1, %2, %3;" : "=l"(d) : "l"(a), "l"(b), "l"(c))
#define PACK2(d,lo,hi)   asm("mov.b64 %0, {%1, %2};" : "=l"(d) : "f"(lo), "f"(hi))
#define UNPACK2(lo,hi,v) asm("mov.b64 {%0, %1}, %2;" : "=f"(lo), "=f"(hi) : "l"(v))

// dot of 8 x f32x2 (16 floats) -> scalar; two parallel chains of 4.
#define DOT16(res, X, Y) do { \
    u64 _pa, _pb; \
    MUL2(_pa, X[0], Y[0]); FMA2(_pa, X[1], Y[1], _pa); \
    FMA2(_pa, X[2], Y[2], _pa); FMA2(_pa, X[3], Y[3], _pa); \
    MUL2(_pb, X[4], Y[4]); FMA2(_pb, X[5], Y[5], _pb); \
    FMA2(_pb, X[6], Y[6], _pb); FMA2(_pb, X[7], Y[7], _pb); \
    float _al, _ah, _bl, _bh; \
    UNPACK2(_al, _ah, _pa); UNPACK2(_bl, _bh, _pb); \
    res = (_al + _ah) + (_bl + _bh); } while(0)

// allreduce over the 4-lane j-group: 2 shfls.
#define RED4(x) do { \
    x += __shfl_xor_sync(0xffffffffu, x, 1); \
    x += __shfl_xor_sync(0xffffffffu, x, 2); } while(0)

// load 8 u64 (16 floats, 64B) from smem/gmem
#define LD8x2(dst, ptr) do { \
    const ulonglong2* _p = (const ulonglong2*)(ptr); \
    ulonglong2 _x0 = _p[0], _x1 = _p[1], _x2 = _p[2], _x3 = _p[3]; \
    dst[0]=_x0.x; dst[1]=_x0.y; dst[2]=_x1.x; dst[3]=_x1.y; \
    dst[4]=_x2.x; dst[5]=_x2.y; dst[6]=_x3.x; dst[7]=_x3.y; } while(0)

__global__ void __launch_bounds__(32, 1) wkv7_kernel(
    const float* __restrict__ rr, const float* __restrict__ ww,
    const float* __restrict__ kk, const float* __restrict__ vv_,
    const float* __restrict__ aa, const float* __restrict__ bb,
    const float* __restrict__ s0, float* __restrict__ y, float* __restrict__ sout)
{
    const int blk   = blockIdx.x;
    const int h     = blk >> 2;
    const int q     = blk & 3;
    const int lane  = threadIdx.x;
    const int lane4 = lane & 3;
    const int g     = lane >> 2;             // 0..7
    const int j0    = lane4 * 16;            // float offset of my j-slice
    const int hbase = h * HS;
    const int row   = q * 16 + g * 2;        // my rows: row, row+1

    __shared__ __align__(16) float ring[DEPTH][STRIDE];

    // State: 2 rows x 16 floats (8 u64 each)
    u64 sA[8], sB[8];
    {
        const float* sp = s0 + ((size_t)h * HS + row) * HS + j0;
        LD8x2(sA, sp);
        LD8x2(sB, sp + HS);
    }

    // cp.async fill: chunks c = lane, lane+32, lane+64 (c<84), 16B each.
    const float* src0 = ((lane >> 4) ? kk : ww) + hbase + (lane & 15) * 4;
    const uint32_t od0 = lane * 4u;
    const float* src1 = ((lane >> 4) ? bb : aa) + hbase + (lane & 15) * 4;
    const uint32_t od1 = 128u + lane * 4u;
    const float* src2 = 0; uint32_t od2 = 0;
    if (lane < 16)      { src2 = rr  + hbase + lane * 4;                 od2 = 256u + lane * 4u; }
    else if (lane < 20) { src2 = vv_ + hbase + q * 16 + (lane - 16) * 4; od2 = 320u + (lane - 16) * 4u; }

#define ISSUE(tt, ss) do { \
    size_t _off = (size_t)(tt) * DIM; \
    uint32_t _sb = smem_u32(&ring[ss][0]); \
    asm volatile("cp.async.cg.shared.global [%0], [%1], 16;" :: "r"(_sb + od0*4u), "l"(src0 + _off)); \
    asm volatile("cp.async.cg.shared.global [%0], [%1], 16;" :: "r"(_sb + od1*4u), "l"(src1 + _off)); \
    if (src2) asm volatile("cp.async.cg.shared.global [%0], [%1], 16;" :: "r"(_sb + od2*4u), "l"(src2 + _off)); \
    asm volatile("cp.async.commit_group;"); \
} while(0)

    #pragma unroll
    for (int i = 0; i < DEPTH; i++) ISSUE(i, i);

    // a_0 direct from gmem
    u64 a2[8];
    LD8x2(a2, aa + hbase + j0);

    float yv0 = 0.f, yv1 = 0.f;               // deferred y partials
    float* const ystore = y + hbase + row;    // float2 per step (lane4==0)

#define STEPBODY(T, SLOT, SLOTN) do { \
    const float* sl  = &ring[SLOT][0]; \
    const float* sln = &ring[SLOTN][0]; \
    /* sa dots (2 rows) + 2-shfl allreduce over 4 lanes */ \
    float sa0, sa1; \
    DOT16(sa0, sA, a2); \
    DOT16(sa1, sB, a2); \
    RED4(sa0); \
    RED4(sa1); \
    /* deferred y_{T-1} (independent; fills shfl slack) */ \
    { \
        float u0 = yv0, u1 = yv1; \
        RED4(u0); \
        RED4(u1); \
        int tprev = (T) - ((T) != 0); \
        if (lane4 == 0) *(float2*)&ystore[(size_t)tprev * DIM] = make_float2(u0, u1); \
    } \
    /* operands: 16 floats each of w,k,b,r (+a_{T+1}); v pair */ \
    u64 w2[8], k2[8], b2[8], r2[8]; \
    LD8x2(w2, sl + j0); \
    LD8x2(k2, sl + 64 + j0); \
    LD8x2(b2, sl + 192 + j0); \
    LD8x2(r2, sl + 256 + j0); \
    const float2 vp = *(const float2*)(sl + 320 + g * 2); \
    LD8x2(a2, sln + 128 + j0); \
    /* update both rows: s = s*w + v*k + sa*b */ \
    u64 v0b, v1b, c0b, c1b; \
    PACK2(v0b, vp.x, vp.x); PACK2(v1b, vp.y, vp.y); \
    PACK2(c0b, sa0, sa0);   PACK2(c1b, sa1, sa1); \
    _Pragma("unroll") \
    for (int i = 0; i < 8; i++) { \
        u64 t0; MUL2(t0, sA[i], w2[i]); FMA2(t0, v0b, k2[i], t0); FMA2(sA[i], c0b, b2[i], t0); \
        u64 t1; MUL2(t1, sB[i], w2[i]); FMA2(t1, v1b, k2[i], t1); FMA2(sB[i], c1b, b2[i], t1); \
    } \
    /* y partials (reduced next step) */ \
    DOT16(yv0, sA, r2); \
    DOT16(yv1, sB, r2); \
} while(0)

    for (int tb = 0; tb < TLEN - DEPTH; tb += DEPTH) {
        #pragma unroll
        for (int u = 0; u < DEPTH; u++) {
            const int t = tb + u;
            asm volatile("cp.async.wait_group 6;");
            __syncwarp();
            STEPBODY(t, u, (u + 1) & (DEPTH - 1));
            ISSUE(t + DEPTH, u);
        }
    }

    asm volatile("cp.async.wait_group 0;");
    __syncwarp();
    #pragma unroll
    for (int u = 0; u < DEPTH; u++) {
        const int t = TLEN - DEPTH + u;
        STEPBODY(t, u, (u + 1) & (DEPTH - 1));   // final a2 prefetch unused
    }

    // Epilogue: y_{TLEN-1}
    {
        RED4(yv0);
        RED4(yv1);
        if (lane4 == 0)
            *(float2*)&ystore[(size_t)(TLEN - 1) * DIM] = make_float2(yv0, yv1);
    }

    // Final state: 2 rows x 16 floats
    {
        float* sp = sout + ((size_t)h * HS + row) * HS + j0;
        ulonglong2* p0 = (ulonglong2*)sp;
        ulonglong2* p1 = (ulonglong2*)(sp + HS);
        ulonglong2 x;
        x.x = sA[0]; x.y = sA[1]; p0[0] = x;  x.x = sA[2]; x.y = sA[3]; p0[1] = x;
        x.x = sA[4]; x.y = sA[5]; p0[2] = x;  x.x = sA[6]; x.y = sA[7]; p0[3] = x;
        x.x = sB[0]; x.y = sB[1]; p1[0] = x;  x.x = sB[2]; x.y = sB[3]; p1[1] = x;
        x.x = sB[4]; x.y = sB[5]; p1[2] = x;  x.x = sB[6]; x.y = sB[7]; p1[3] = x;
    }
}

extern "C" void kernel_launch(void* const* d_in, const int* in_sizes, int n_in,
                              void* d_out, int out_size) {
    int o = (n_in >= 8) ? 1 : 0;
    const float* r  = (const float*)d_in[o + 0];
    const float* w  = (const float*)d_in[o + 1];
    const float* k  = (const float*)d_in[o + 2];
    const float* v  = (const float*)d_in[o + 3];
    const float* a  = (const float*)d_in[o + 4];
    const float* b  = (const float*)d_in[o + 5];
    const float* s0 = (const float*)d_in[o + 6];

    float* y    = (float*)d_out;                  // x: [T, H, 1, N]
    float* sout = y + (size_t)TLEN * DIM;         // state2_out: [H, N, N]

    wkv7_kernel<<<128, 32>>>(r, w, k, v, a, b, s0, y, sout);
}

// round 16
// speedup vs baseline: 1.4860x; 1.4118x over previous
#include <cuda_runtime.h>
#include <cstdint>

#define TLEN 4096
#define NH 32
#define HS 64
#define DIM (NH*HS)
#define DEPTH 8
#define STRIDE 336   // floats/slot: w64|k64|a64|b64|r64|v8|pad

// R6 layout (best: 673us): grid=128 (32 heads x 4 quarters), block=64 =
// 2 warps; warp = 4 groups x 8 lanes; lane owns TWO rows' j-slices
// (f32x2-packed). Per-warp cp.async ring DEPTH=8, 8x-unrolled loop.
// Changes vs R6:
//  - y reductions BATCHED per 8 steps: reduce-scatter butterfly (7 shfl for
//    8 reductions; step tb+L lands on lane L) instead of per-step RED8.
//  - ONE cp.async.wait_group + __syncwarp per PAIR of steps (ring lookahead
//    already guarantees slots t..t+2 complete at wait_group 5).

__device__ __forceinline__ uint32_t smem_u32(const void* p) {
    return (uint32_t)__cvta_generic_to_shared(p);
}

typedef unsigned long long u64;

#define MUL2(d,a,b)   asm("mul.rn.f32x2 %0, %1, %2;"     : "=l"(d) : "l"(a), "l"(b))
#define FMA2(d,a,b,c) asm("fma.rn.f32x2 %0, %1, %2, %3;" : "=l"(d) : "l"(a), "l"(b), "l"(c))
#define PACK2(d,lo,hi)   asm("mov.b64 %0, {%1, %2};" : "=l"(d) : "f"(lo), "f"(hi))
#define UNPACK2(lo,hi,v) asm("mov.b64 {%0, %1}, %2;" : "=f"(lo), "=f"(hi) : "l"(v))

#define DOT8(res, X, Y) do { \
    u64 _p; MUL2(_p, X[0], Y[0]); FMA2(_p, X[1], Y[1], _p); \
    FMA2(_p, X[2], Y[2], _p);     FMA2(_p, X[3], Y[3], _p); \
    float _lo, _hi; UNPACK2(_lo, _hi, _p); res = _lo + _hi; } while(0)

#define RED8(x) do { \
    x += __shfl_xor_sync(0xffffffffu, x, 1); \
    x += __shfl_xor_sync(0xffffffffu, x, 2); \
    x += __shfl_xor_sync(0xffffffffu, x, 4); } while(0)

#define LD4x2(dst, ptr) do { \
    const ulonglong2* _p = (const ulonglong2*)(ptr); \
    ulonglong2 _x0 = _p[0], _x1 = _p[1]; \
    dst[0]=_x0.x; dst[1]=_x0.y; dst[2]=_x1.x; dst[3]=_x1.y; } while(0)

// Reduce-scatter 8 values over the 8-lane group: value index L ends fully
// summed on lane8==L. 7 shfls, 7 adds.
__device__ __forceinline__ float rs8(const float* v, bool b4, bool b2, bool b1) {
    float t[4];
    #pragma unroll
    for (int i = 0; i < 4; i++) {
        float s = b4 ? v[i] : v[i + 4];
        float r = __shfl_xor_sync(0xffffffffu, s, 4);
        t[i] = (b4 ? v[i + 4] : v[i]) + r;
    }
    float u[2];
    #pragma unroll
    for (int i = 0; i < 2; i++) {
        float s = b2 ? t[i] : t[i + 2];
        float r = __shfl_xor_sync(0xffffffffu, s, 2);
        u[i] = (b2 ? t[i + 2] : t[i]) + r;
    }
    float s = b1 ? u[0] : u[1];
    float r = __shfl_xor_sync(0xffffffffu, s, 1);
    return (b1 ? u[1] : u[0]) + r;
}

__global__ void __launch_bounds__(64, 1) wkv7_kernel(
    const float* __restrict__ rr, const float* __restrict__ ww,
    const float* __restrict__ kk, const float* __restrict__ vv_,
    const float* __restrict__ aa, const float* __restrict__ bb,
    const float* __restrict__ s0, float* __restrict__ y, float* __restrict__ sout)
{
    const int blk   = blockIdx.x;
    const int h     = blk >> 2;
    const int q     = blk & 3;
    const int tid   = threadIdx.x;
    const int warp  = tid >> 5;
    const int lane  = tid & 31;
    const int lane8 = lane & 7;
    const int g     = lane >> 3;
    const int j0    = lane8 * 8;
    const int hbase = h * HS;
    const int r0    = q * 16 + warp * 8 + g * 2;
    const bool b4   = (lane8 & 4) != 0;
    const bool b2   = (lane8 & 2) != 0;
    const bool b1   = (lane8 & 1) != 0;

    __shared__ __align__(16) float ring[2][DEPTH][STRIDE];

    u64 sA[4], sB[4];
    {
        const float* sp = s0 + ((size_t)h * HS + r0) * HS + j0;
        LD4x2(sA, sp);
        LD4x2(sB, sp + HS);
    }

    // cp.async lane routing (3 x 16B per lane per step)
    const float *g1, *g2, *g3 = 0;
    uint32_t o1, o2, o3 = 0;
    if (lane < 16) { g1 = ww + hbase + lane * 4;        o1 = 0   + lane * 4; }
    else           { g1 = kk + hbase + (lane - 16) * 4; o1 = 64  + (lane - 16) * 4; }
    if (lane < 16) { g2 = aa + hbase + lane * 4;        o2 = 128 + lane * 4; }
    else           { g2 = bb + hbase + (lane - 16) * 4; o2 = 192 + (lane - 16) * 4; }
    if (lane < 16)      { g3 = rr + hbase + lane * 4;                      o3 = 256 + lane * 4; }
    else if (lane < 18) { g3 = vv_ + hbase + q * 16 + warp * 8 + (lane - 16) * 4; o3 = 320 + (lane - 16) * 4; }

#define ISSUE(tt, ss) do { \
    size_t _off = (size_t)(tt) * DIM; \
    uint32_t _sb = smem_u32(&ring[warp][ss][0]); \
    asm volatile("cp.async.cg.shared.global [%0], [%1], 16;" :: "r"(_sb + o1*4u), "l"(g1 + _off)); \
    asm volatile("cp.async.cg.shared.global [%0], [%1], 16;" :: "r"(_sb + o2*4u), "l"(g2 + _off)); \
    if (g3) asm volatile("cp.async.cg.shared.global [%0], [%1], 16;" :: "r"(_sb + o3*4u), "l"(g3 + _off)); \
    asm volatile("cp.async.commit_group;"); \
} while(0)

    #pragma unroll
    for (int i = 0; i < DEPTH; i++) ISSUE(i, i);

    // a_0 direct from gmem
    u64 a2[4];
    LD4x2(a2, aa + hbase + j0);

    float ypA[8], ypB[8];                    // per-step y partials (one block)
    float* const ybase = y + hbase + r0;

// Step body. U = step index within 8-block (compile-time), SLOT = slot of t,
// SLOTN = slot of t+1 (a-prefetch). NO wait here (done per pair outside).
#define STEPBODY(U, SLOT, SLOTN) do { \
    const float* sl  = &ring[warp][SLOT][0]; \
    const float* sln = &ring[warp][SLOTN][0]; \
    float sa0, sa1; \
    DOT8(sa0, sA, a2); \
    DOT8(sa1, sB, a2); \
    RED8(sa0); \
    RED8(sa1); \
    u64 w2[4], k2[4], b2r[4], r2[4]; \
    LD4x2(w2, sl + j0); \
    LD4x2(k2, sl + 64 + j0); \
    LD4x2(b2r, sl + 192 + j0); \
    LD4x2(r2, sl + 256 + j0); \
    const float2 vpair = *(const float2*)(sl + 320 + g * 2); \
    LD4x2(a2, sln + 128 + j0); \
    u64 v0b, v1b, sa0b, sa1b; \
    PACK2(v0b, vpair.x, vpair.x); PACK2(v1b, vpair.y, vpair.y); \
    PACK2(sa0b, sa0, sa0);        PACK2(sa1b, sa1, sa1); \
    _Pragma("unroll") \
    for (int i = 0; i < 4; i++) { \
        u64 t0; MUL2(t0, sA[i], w2[i]); \
        FMA2(t0, v0b, k2[i], t0); \
        FMA2(sA[i], sa0b, b2r[i], t0); \
        u64 t1; MUL2(t1, sB[i], w2[i]); \
        FMA2(t1, v1b, k2[i], t1); \
        FMA2(sB[i], sa1b, b2r[i], t1); \
    } \
    DOT8(ypA[U], sA, r2); \
    DOT8(ypB[U], sB, r2); \
} while(0)

// Batched y: reduce-scatter the 8 partials; lane8==L holds y_{tb+L}.
#define YFLUSH(TB) do { \
    float yA = rs8(ypA, b4, b2, b1); \
    float yB = rs8(ypB, b4, b2, b1); \
    float* yp = ybase + (size_t)((TB) + lane8) * DIM; \
    yp[0] = yA; \
    yp[1] = yB; \
} while(0)

    // Main: 4 pairs per 8-step block; ONE wait+syncwarp per pair.
    for (int tb = 0; tb < TLEN - DEPTH; tb += DEPTH) {
        #pragma unroll
        for (int pu = 0; pu < 4; pu++) {
            const int t = tb + 2 * pu;
            asm volatile("cp.async.wait_group 5;");
            __syncwarp();
            STEPBODY(2 * pu,     2 * pu,      2 * pu + 1);
            STEPBODY(2 * pu + 1, 2 * pu + 1, (2 * pu + 2) & 7);
            ISSUE(t + DEPTH, 2 * pu);
            ISSUE(t + DEPTH + 1, 2 * pu + 1);
        }
        YFLUSH(tb);
    }

    // Tail: all staged; final a-prefetch (slot 0) is read but unused.
    asm volatile("cp.async.wait_group 0;");
    __syncwarp();
    #pragma unroll
    for (int pu = 0; pu < 4; pu++) {
        STEPBODY(2 * pu,     2 * pu,      2 * pu + 1);
        STEPBODY(2 * pu + 1, 2 * pu + 1, (2 * pu + 2) & 7);
    }
    YFLUSH(TLEN - DEPTH);

    // Final state
    {
        float* sp = sout + ((size_t)h * HS + r0) * HS + j0;
        ulonglong2* p0 = (ulonglong2*)sp;
        ulonglong2* p1 = (ulonglong2*)(sp + HS);
        ulonglong2 x;
        x.x = sA[0]; x.y = sA[1]; p0[0] = x;
        x.x = sA[2]; x.y = sA[3]; p0[1] = x;
        x.x = sB[0]; x.y = sB[1]; p1[0] = x;
        x.x = sB[2]; x.y = sB[3]; p1[1] = x;
    }
}

extern "C" void kernel_launch(void* const* d_in, const int* in_sizes, int n_in,
                              void* d_out, int out_size) {
    int o = (n_in >= 8) ? 1 : 0;
    const float* r  = (const float*)d_in[o + 0];
    const float* w  = (const float*)d_in[o + 1];
    const float* k  = (const float*)d_in[o + 2];
    const float* v  = (const float*)d_in[o + 3];
    const float* a  = (const float*)d_in[o + 4];
    const float* b  = (const float*)d_in[o + 5];
    const float* s0 = (const float*)d_in[o + 6];

    float* y    = (float*)d_out;                  // x: [T, H, 1, N]
    float* sout = y + (size_t)TLEN * DIM;         // state2_out: [H, N, N]

    wkv7_kernel<<<128, 64>>>(r, w, k, v, a, b, s0, y, sout);
}